// round 5
// baseline (speedup 1.0000x reference)
#include <cuda_runtime.h>
#include <cstdint>

// YOLO decode: persistent warps, cp.async double-buffered 16-box tiles,
// two lanes cooperate per box (split 80-logit argmax).
// Inputs: small [104,104,3,85] f32, middle [208,208,3,85] f32,
//         large [416,416,3,85] f32, pre_scale [6,3,2] f32.
// Output: [681408, 6] f32, rows zeroed where conf <= 0.5.

constexpr int N_SMALL  = 104 * 104 * 3;   // 32448  (mult of 16)
constexpr int N_MIDDLE = 208 * 208 * 3;   // 129792 (mult of 16)
constexpr int N_LARGE  = 416 * 416 * 3;   // 519168 (mult of 16)
constexpr int N_TOTAL  = N_SMALL + N_MIDDLE + N_LARGE;  // 681408
constexpr int TILE     = 16;              // boxes per warp-tile
constexpr int N_TILES  = N_TOTAL / TILE;  // 42588
constexpr int WPB      = 2;               // 64 thr, 21.8KB smem -> 10 blocks/SM
constexpr int NBLK     = 148 * 10;        // 1480 persistent blocks
constexpr int TOTW     = NBLK * WPB;      // 2960 warps, ~14.4 tiles each
constexpr int V4_PER_TILE = TILE * 85 / 4;  // 340 float4

#define FULLMASK 0xffffffffu

static __device__ __forceinline__ void cp16(uint32_t dst_smem, const float4* src) {
    asm volatile("cp.async.cg.shared.global [%0], [%1], 16;\n"
                 :: "r"(dst_smem), "l"(src));
}
static __device__ __forceinline__ void cp_commit() {
    asm volatile("cp.async.commit_group;\n" ::: "memory");
}
template<int N>
static __device__ __forceinline__ void cp_wait() {
    asm volatile("cp.async.wait_group %0;\n" :: "n"(N) : "memory");
}

static __device__ __forceinline__ void tile_level(
    int t, const float* small, const float* middle, const float* large,
    const float*& in, int& lvl, int& r0)
{
    const int boxBase = t * TILE;
    if (boxBase < N_SMALL)                 { in = small;  lvl = 0; r0 = boxBase; }
    else if (boxBase < N_SMALL + N_MIDDLE) { in = middle; lvl = 1; r0 = boxBase - N_SMALL; }
    else                                   { in = large;  lvl = 2; r0 = boxBase - N_SMALL - N_MIDDLE; }
}

template<int S, int DECT>
static __device__ __forceinline__ void boxxform(
    int r, float tx, float ty, float tw, float th,
    const float* __restrict__ ps,
    float& x, float& y, float& w, float& h)
{
    const int i = r / (3 * S);
    const int j = (r / 3) % S;
    const int a = r % 3;
    constexpr float invS = 1.0f / (float)S;
    x = (1.0f / (1.0f + __expf(-tx)) + (float)i) * invS;
    y = (1.0f / (1.0f + __expf(-ty)) + (float)j) * invS;
    const float aw = __ldg(ps + ((DECT * 3 + a) * 2 + 0));
    const float ah = __ldg(ps + ((DECT * 3 + a) * 2 + 1));
    w = __expf(tw) * aw * (1.0f / 416.0f);
    h = __expf(th) * ah * (1.0f / 416.0f);
}

__global__ __launch_bounds__(32 * WPB) void HEAD_kernel(
    const float* __restrict__ small,
    const float* __restrict__ middle,
    const float* __restrict__ large,
    const float* __restrict__ pre_scale,
    float* __restrict__ out)
{
    __shared__ float4 sm[WPB][2][V4_PER_TILE];

    const int lane = threadIdx.x & 31;
    const int wIn  = threadIdx.x >> 5;
    const int gw   = blockIdx.x * WPB + wIn;

    const uint32_t sbase[2] = {
        (uint32_t)__cvta_generic_to_shared(&sm[wIn][0][0]),
        (uint32_t)__cvta_generic_to_shared(&sm[wIn][1][0])
    };

    auto stage = [&](int t, int buf) {
        const float* in; int lvl, r0;
        tile_level(t, small, middle, large, in, lvl, r0);
        const float4* g4 = (const float4*)(in + (size_t)r0 * 85);
        const uint32_t sb = sbase[buf];
        #pragma unroll
        for (int j = 0; j < 11; j++) {
            const int idx = lane + 32 * j;
            if (idx < V4_PER_TILE) cp16(sb + idx * 16, g4 + idx);
        }
        cp_commit();
    };

    auto compute = [&](int t, int buf) {
        const float* inu; int lvl, r0;
        tile_level(t, small, middle, large, inu, lvl, r0);

        const int m = lane >> 1;          // box within tile
        const int h = lane & 1;           // logit half: [0,40) or [40,80)
        const float* b = (const float*)&sm[wIn][buf][0] + m * 85;

        // ---- per-lane argmax over its 40-logit half (first-occurrence) ----
        const float* lb = b + 5 + h * 40;
        float best = lb[0];  int bi = 0;
        #pragma unroll
        for (int k = 1; k < 40; k++) {
            const float v = lb[k];
            if (v > best) { best = v; bi = k; }
        }

        // ---- pair combine: strict > on high half keeps low-half ties ----
        const float obest = __shfl_xor_sync(FULLMASK, best, 1);
        const int   obi   = __shfl_xor_sync(FULLMASK, bi, 1);

        if (h == 0) {
            const int cls = (obest > best) ? (40 + obi) : bi;

            const float conf = b[0];
            const float tx = b[1], ty = b[2], tw = b[3], th = b[4];

            const int r = r0 + m;
            float x, y, w, wh;
            if (lvl == 0)      boxxform<104, 3>(r, tx, ty, tw, th, pre_scale, x, y, w, wh);
            else if (lvl == 1) boxxform<208, 4>(r, tx, ty, tw, th, pre_scale, x, y, w, wh);
            else               boxxform<416, 5>(r, tx, ty, tw, th, pre_scale, x, y, w, wh);

            const float mk = (conf > 0.5f) ? 1.0f : 0.0f;
            float* o = out + (size_t)(t * TILE + m) * 6;
            o[0] = x  * mk;
            o[1] = y  * mk;
            o[2] = w  * mk;
            o[3] = wh * mk;
            o[4] = (float)cls * mk;
            o[5] = conf * mk;
        }
    };

    int t = gw;
    if (t >= N_TILES) return;
    stage(t, 0);
    int cur = 0;

    while (true) {
        const int tn = t + TOTW;
        const bool have_next = (tn < N_TILES);
        if (have_next) {
            stage(tn, cur ^ 1);
            cp_wait<1>();
        } else {
            cp_wait<0>();
        }
        __syncwarp();
        compute(t, cur);
        __syncwarp();
        if (!have_next) break;
        t = tn;
        cur ^= 1;
    }
}

extern "C" void kernel_launch(void* const* d_in, const int* in_sizes, int n_in,
                              void* d_out, int out_size)
{
    const float* small     = (const float*)d_in[0];
    const float* middle    = (const float*)d_in[1];
    const float* large     = (const float*)d_in[2];
    const float* pre_scale = (const float*)d_in[3];
    float* out = (float*)d_out;

    HEAD_kernel<<<NBLK, 32 * WPB>>>(small, middle, large, pre_scale, out);
}